// round 1
// baseline (speedup 1.0000x reference)
#include <cuda_runtime.h>
#include <cstdint>

#define BATCH 16384
#define IN_F  512

// Ping-pong scratch (max layer width 2048). Static device globals: allowed.
__device__ float g_buf0[BATCH * 2048];
__device__ float g_buf1[BATCH * 2048];

__device__ __forceinline__ unsigned f2tf32(float f) {
    unsigned r;
    asm("cvt.rna.tf32.f32 %0, %1;" : "=r"(r) : "f"(f));
    return r;
}

// ---------------------------------------------------------------------------
// Cross layer: h = x * (x . cross_w) + cross_b + x     (one warp per row)
// ---------------------------------------------------------------------------
__global__ void cross_kernel(const float* __restrict__ x,
                             const float* __restrict__ cw,
                             const float* __restrict__ cb,
                             float* __restrict__ out) {
    int gw   = (blockIdx.x * blockDim.x + threadIdx.x) >> 5;
    int lane = threadIdx.x & 31;
    if (gw >= BATCH) return;
    const float4* xr  = (const float4*)(x + (size_t)gw * IN_F);
    const float4* cwr = (const float4*)cw;
    float4 xv[4];
    float s = 0.f;
#pragma unroll
    for (int c = 0; c < 4; c++) {
        xv[c] = xr[c * 32 + lane];
        float4 w = cwr[c * 32 + lane];
        s += xv[c].x * w.x + xv[c].y * w.y + xv[c].z * w.z + xv[c].w * w.w;
    }
#pragma unroll
    for (int o = 16; o > 0; o >>= 1) s += __shfl_xor_sync(0xffffffffu, s, o);
    const float4* cbr = (const float4*)cb;
    float4* outr = (float4*)(out + (size_t)gw * IN_F);
#pragma unroll
    for (int c = 0; c < 4; c++) {
        float4 b = cbr[c * 32 + lane];
        float4 r;
        r.x = fmaf(xv[c].x, s, b.x) + xv[c].x;
        r.y = fmaf(xv[c].y, s, b.y) + xv[c].y;
        r.z = fmaf(xv[c].z, s, b.z) + xv[c].z;
        r.w = fmaf(xv[c].w, s, b.w) + xv[c].w;
        outr[c * 32 + lane] = r;
    }
}

// ---------------------------------------------------------------------------
// TF32 tensor-core GEMM:  C[M,N] = relu(A[M,K] @ W[N,K]^T + bias)
// BM=128, BN=128, BK=32; 256 threads (8 warps, 4x2), warp tile 32x64,
// m16n8k8 frags (2 along M, 8 along N). Smem row stride 36 words ->
// conflict-free fragment loads and 16B-aligned vector stores.
// ---------------------------------------------------------------------------
#define BM 128
#define BN 128
#define BK 32
#define LDS_W 36   // 36*4 = 144 bytes, 16B-aligned rows, conflict-free frags

#define MMA_TF32(c, a, b)                                                     \
    asm volatile(                                                             \
        "mma.sync.aligned.m16n8k8.row.col.f32.tf32.tf32.f32 "                 \
        "{%0,%1,%2,%3},{%4,%5,%6,%7},{%8,%9},{%0,%1,%2,%3};"                  \
        : "+f"(c[0]), "+f"(c[1]), "+f"(c[2]), "+f"(c[3])                      \
        : "r"(a[0]), "r"(a[1]), "r"(a[2]), "r"(a[3]), "r"(b[0]), "r"(b[1]))

template <bool RELU>
__global__ __launch_bounds__(256, 2)
void gemm_tf32_bias(const float* __restrict__ A,
                    const float* __restrict__ W,
                    const float* __restrict__ bias,
                    float* __restrict__ C,
                    int K, int N) {
    __shared__ unsigned As[BM * LDS_W];
    __shared__ unsigned Bs[BN * LDS_W];

    const int row0 = blockIdx.y * BM;
    const int col0 = blockIdx.x * BN;
    const int tid  = threadIdx.x;
    const int warp = tid >> 5, lane = tid & 31;
    const int wm = warp >> 1, wn = warp & 1;   // 4 x 2 warp grid
    const int gid = lane >> 2, tg = lane & 3;  // group id / thread-in-group

    float acc[2][8][4];
#pragma unroll
    for (int mi = 0; mi < 2; mi++)
#pragma unroll
        for (int ni = 0; ni < 8; ni++)
#pragma unroll
            for (int e = 0; e < 4; e++) acc[mi][ni][e] = 0.f;

    for (int kt = 0; kt < K; kt += BK) {
        // --- load A tile (BM x BK) and B tile (BN x BK), convert to tf32 ---
#pragma unroll
        for (int t = 0; t < 4; t++) {
            int i  = tid + t * 256;
            int m  = i >> 3;
            int k4 = (i & 7) << 2;
            float4 v = *(const float4*)(A + (size_t)(row0 + m) * K + kt + k4);
            *(uint4*)&As[m * LDS_W + k4] =
                make_uint4(f2tf32(v.x), f2tf32(v.y), f2tf32(v.z), f2tf32(v.w));
        }
#pragma unroll
        for (int t = 0; t < 4; t++) {
            int i  = tid + t * 256;
            int n  = i >> 3;
            int k4 = (i & 7) << 2;
            float4 v = *(const float4*)(W + (size_t)(col0 + n) * K + kt + k4);
            *(uint4*)&Bs[n * LDS_W + k4] =
                make_uint4(f2tf32(v.x), f2tf32(v.y), f2tf32(v.z), f2tf32(v.w));
        }
        __syncthreads();

        // --- compute: 4 k-steps of 8 ---
#pragma unroll
        for (int k0 = 0; k0 < BK; k0 += 8) {
            unsigned a[2][4], b[8][2];
#pragma unroll
            for (int mi = 0; mi < 2; mi++) {
                int r = wm * 32 + mi * 16 + gid;
                a[mi][0] = As[r * LDS_W + k0 + tg];
                a[mi][1] = As[(r + 8) * LDS_W + k0 + tg];
                a[mi][2] = As[r * LDS_W + k0 + tg + 4];
                a[mi][3] = As[(r + 8) * LDS_W + k0 + tg + 4];
            }
#pragma unroll
            for (int ni = 0; ni < 8; ni++) {
                int n = wn * 64 + ni * 8 + gid;
                b[ni][0] = Bs[n * LDS_W + k0 + tg];
                b[ni][1] = Bs[n * LDS_W + k0 + tg + 4];
            }
#pragma unroll
            for (int mi = 0; mi < 2; mi++)
#pragma unroll
                for (int ni = 0; ni < 8; ni++)
                    MMA_TF32(acc[mi][ni], a[mi], b[ni]);
        }
        __syncthreads();
    }

    // --- epilogue: bias + relu, float2 stores ---
#pragma unroll
    for (int mi = 0; mi < 2; mi++) {
#pragma unroll
        for (int ni = 0; ni < 8; ni++) {
            int r  = row0 + wm * 32 + mi * 16 + gid;
            int cl = col0 + wn * 64 + ni * 8 + 2 * tg;
            float b0 = bias[cl], b1 = bias[cl + 1];
            float v0 = acc[mi][ni][0] + b0;
            float v1 = acc[mi][ni][1] + b1;
            float v2 = acc[mi][ni][2] + b0;
            float v3 = acc[mi][ni][3] + b1;
            if (RELU) {
                v0 = fmaxf(v0, 0.f); v1 = fmaxf(v1, 0.f);
                v2 = fmaxf(v2, 0.f); v3 = fmaxf(v3, 0.f);
            }
            *(float2*)(C + (size_t)r * N + cl)       = make_float2(v0, v1);
            *(float2*)(C + (size_t)(r + 8) * N + cl) = make_float2(v2, v3);
        }
    }
}

// ---------------------------------------------------------------------------
// Final head: out[b] = h[b,:] . Wo[0,:] + bo   (one warp per row, K=512)
// ---------------------------------------------------------------------------
__global__ void gemv_kernel(const float* __restrict__ h,
                            const float* __restrict__ w,
                            const float* __restrict__ b,
                            float* __restrict__ out) {
    int gw   = (blockIdx.x * blockDim.x + threadIdx.x) >> 5;
    int lane = threadIdx.x & 31;
    if (gw >= BATCH) return;
    const float4* hr = (const float4*)(h + (size_t)gw * 512);
    const float4* wr = (const float4*)w;
    float s = 0.f;
#pragma unroll
    for (int c = 0; c < 4; c++) {
        float4 hv = hr[c * 32 + lane];
        float4 wv = wr[c * 32 + lane];
        s += hv.x * wv.x + hv.y * wv.y + hv.z * wv.z + hv.w * wv.w;
    }
#pragma unroll
    for (int o = 16; o > 0; o >>= 1) s += __shfl_xor_sync(0xffffffffu, s, o);
    if (lane == 0) out[gw] = s + b[0];
}

// ---------------------------------------------------------------------------
extern "C" void kernel_launch(void* const* d_in, const int* in_sizes, int n_in,
                              void* d_out, int out_size) {
    (void)in_sizes; (void)n_in; (void)out_size;
    const float* x  = (const float*)d_in[0];
    const float* cw = (const float*)d_in[1];
    const float* cb = (const float*)d_in[2];
    const float* W1 = (const float*)d_in[3];  const float* b1 = (const float*)d_in[4];
    const float* W2 = (const float*)d_in[5];  const float* b2 = (const float*)d_in[6];
    const float* W3 = (const float*)d_in[7];  const float* b3 = (const float*)d_in[8];
    const float* W4 = (const float*)d_in[9];  const float* b4 = (const float*)d_in[10];
    const float* Wo = (const float*)d_in[11]; const float* bo = (const float*)d_in[12];

    float *buf0, *buf1;
    cudaGetSymbolAddress((void**)&buf0, g_buf0);
    cudaGetSymbolAddress((void**)&buf1, g_buf1);

    // cross: 16384 warps
    cross_kernel<<<BATCH / 8, 256>>>(x, cw, cb, buf0);

    // 4 hidden layers (M=16384 rows; grid = (N/128, M/128))
    gemm_tf32_bias<true><<<dim3(2048 / BN, BATCH / BM), 256>>>(buf0, W1, b1, buf1,  512, 2048);
    gemm_tf32_bias<true><<<dim3(2048 / BN, BATCH / BM), 256>>>(buf1, W2, b2, buf0, 2048, 2048);
    gemm_tf32_bias<true><<<dim3(1024 / BN, BATCH / BM), 256>>>(buf0, W3, b3, buf1, 2048, 1024);
    gemm_tf32_bias<true><<<dim3( 512 / BN, BATCH / BM), 256>>>(buf1, W4, b4, buf0, 1024,  512);

    // head
    gemv_kernel<<<BATCH / 8, 256>>>(buf0, Wo, bo, (float*)d_out);
}

// round 3
// speedup vs baseline: 1.1301x; 1.1301x over previous
#include <cuda_runtime.h>
#include <cstdint>

#define BATCH 16384
#define IN_F  512

// Ping-pong scratch (max layer width 2048) + pre-rounded tf32 weights.
__device__ float g_buf0[BATCH * 2048];
__device__ float g_buf1[BATCH * 2048];
__device__ float g_w1[2048 * 512];
__device__ float g_w2[2048 * 2048];
__device__ float g_w3[1024 * 2048];
__device__ float g_w4[512 * 1024];

__device__ __forceinline__ unsigned f2tf32(float f) {
    unsigned r;
    asm("cvt.rna.tf32.f32 %0, %1;" : "=r"(r) : "f"(f));
    return r;
}
__device__ __forceinline__ uint32_t smem_u32(const void* p) {
    uint32_t a;
    asm("{ .reg .u64 t; cvta.to.shared.u64 t, %1; cvt.u32.u64 %0, t; }"
        : "=r"(a) : "l"(p));
    return a;
}

// ---------------------------------------------------------------------------
// Weight pre-round: out = tf32(in), vectorized
// ---------------------------------------------------------------------------
__global__ void cvt_tf32_kernel(const float* __restrict__ in,
                                float* __restrict__ out, int n4) {
    int i = blockIdx.x * blockDim.x + threadIdx.x;
    if (i >= n4) return;
    float4 v = ((const float4*)in)[i];
    float4 o;
    o.x = __uint_as_float(f2tf32(v.x));
    o.y = __uint_as_float(f2tf32(v.y));
    o.z = __uint_as_float(f2tf32(v.z));
    o.w = __uint_as_float(f2tf32(v.w));
    ((float4*)out)[i] = o;
}

// ---------------------------------------------------------------------------
// Cross layer: h = tf32( x * (x . cross_w) + cross_b + x )  (one warp per row)
// ---------------------------------------------------------------------------
__global__ void cross_kernel(const float* __restrict__ x,
                             const float* __restrict__ cw,
                             const float* __restrict__ cb,
                             float* __restrict__ out) {
    int gw   = (blockIdx.x * blockDim.x + threadIdx.x) >> 5;
    int lane = threadIdx.x & 31;
    if (gw >= BATCH) return;
    const float4* xr  = (const float4*)(x + (size_t)gw * IN_F);
    const float4* cwr = (const float4*)cw;
    float4 xv[4];
    float s = 0.f;
#pragma unroll
    for (int c = 0; c < 4; c++) {
        xv[c] = xr[c * 32 + lane];
        float4 w = cwr[c * 32 + lane];
        s += xv[c].x * w.x + xv[c].y * w.y + xv[c].z * w.z + xv[c].w * w.w;
    }
#pragma unroll
    for (int o = 16; o > 0; o >>= 1) s += __shfl_xor_sync(0xffffffffu, s, o);
    const float4* cbr = (const float4*)cb;
    float4* outr = (float4*)(out + (size_t)gw * IN_F);
#pragma unroll
    for (int c = 0; c < 4; c++) {
        float4 b = cbr[c * 32 + lane];
        float4 r;
        r.x = __uint_as_float(f2tf32(fmaf(xv[c].x, s, b.x) + xv[c].x));
        r.y = __uint_as_float(f2tf32(fmaf(xv[c].y, s, b.y) + xv[c].y));
        r.z = __uint_as_float(f2tf32(fmaf(xv[c].z, s, b.z) + xv[c].z));
        r.w = __uint_as_float(f2tf32(fmaf(xv[c].w, s, b.w) + xv[c].w));
        outr[c * 32 + lane] = r;
    }
}

// ---------------------------------------------------------------------------
// TF32 tensor-core GEMM with cp.async 3-stage pipeline.
//   C[M,N] = relu(A[M,K] @ W[N,K]^T + bias),  A/W pre-rounded to tf32.
// BM=BN=128, BK=32; 256 threads (8 warps 4x2), warp tile 32x64 (m16n8k8).
// Smem row stride 36 words -> conflict-free fragment loads.
// ---------------------------------------------------------------------------
#define BM 128
#define BN 128
#define BK 32
#define LDS_W 36
#define NSTAGE 3
#define TILE_WORDS (BM * LDS_W)              // one operand tile: 4608 words
#define STAGE_WORDS (2 * TILE_WORDS)         // A + B: 9216 words = 36864 B
#define SMEM_BYTES (NSTAGE * STAGE_WORDS * 4)  // 110592 B

#define MMA_TF32(c, a, b)                                                     \
    asm volatile(                                                             \
        "mma.sync.aligned.m16n8k8.row.col.f32.tf32.tf32.f32 "                 \
        "{%0,%1,%2,%3},{%4,%5,%6,%7},{%8,%9},{%0,%1,%2,%3};"                  \
        : "+f"(c[0]), "+f"(c[1]), "+f"(c[2]), "+f"(c[3])                      \
        : "r"(a[0]), "r"(a[1]), "r"(a[2]), "r"(a[3]), "r"(b[0]), "r"(b[1]))

#define CP16(dst, src)                                                        \
    asm volatile("cp.async.cg.shared.global [%0], [%1], 16;"                  \
                 :: "r"(dst), "l"(src))

template <bool ROUND>
__global__ __launch_bounds__(256, 2)
void gemm_tf32(const float* __restrict__ A, const float* __restrict__ W,
               const float* __restrict__ bias, float* __restrict__ C,
               int K, int N) {
    extern __shared__ unsigned smem[];
    const uint32_t sbase = smem_u32(smem);
    const int tid = threadIdx.x;
    const int warp = tid >> 5, lane = tid & 31;
    const int wm = warp >> 1, wn = warp & 1;
    const int gid = lane >> 2, tg = lane & 3;
    const int row0 = blockIdx.y * BM;
    const int col0 = blockIdx.x * BN;

    // per-thread load coords: 4 chunks of A, 4 of B per stage
    const int lm = tid >> 3;            // 0..31 base row
    const int lk4 = (tid & 7) << 2;     // 0,4,..,28 (float offset)
    const float* Abase = A + (size_t)(row0 + lm) * K + lk4;
    const float* Wbase = W + (size_t)(col0 + lm) * K + lk4;
    const uint32_t soff = (lm * LDS_W + lk4) * 4;   // byte offset in tile

    const int T = K / BK;

#define ISSUE_STAGE(kt)                                                       \
    do {                                                                      \
        uint32_t _sA = sbase + ((kt) % NSTAGE) * (STAGE_WORDS * 4);           \
        uint32_t _sB = _sA + TILE_WORDS * 4;                                  \
        const float* _Ag = Abase + (size_t)(kt) * BK;                         \
        const float* _Wg = Wbase + (size_t)(kt) * BK;                         \
        CP16(_sA + soff,                      _Ag);                           \
        CP16(_sA + soff + 32 * LDS_W * 4,     _Ag + (size_t)32 * K);          \
        CP16(_sA + soff + 64 * LDS_W * 4,     _Ag + (size_t)64 * K);          \
        CP16(_sA + soff + 96 * LDS_W * 4,     _Ag + (size_t)96 * K);          \
        CP16(_sB + soff,                      _Wg);                           \
        CP16(_sB + soff + 32 * LDS_W * 4,     _Wg + (size_t)32 * K);          \
        CP16(_sB + soff + 64 * LDS_W * 4,     _Wg + (size_t)64 * K);          \
        CP16(_sB + soff + 96 * LDS_W * 4,     _Wg + (size_t)96 * K);          \
        asm volatile("cp.async.commit_group;" ::: "memory");                  \
    } while (0)

    float acc[2][8][4];
#pragma unroll
    for (int mi = 0; mi < 2; mi++)
#pragma unroll
        for (int ni = 0; ni < 8; ni++)
#pragma unroll
            for (int e = 0; e < 4; e++) acc[mi][ni][e] = 0.f;

    ISSUE_STAGE(0);
    ISSUE_STAGE(1);

    for (int kt = 0; kt < T; kt++) {
        if (kt < T - 1)
            asm volatile("cp.async.wait_group 1;" ::: "memory");
        else
            asm volatile("cp.async.wait_group 0;" ::: "memory");
        __syncthreads();

        if (kt + 2 < T) ISSUE_STAGE(kt + 2);

        const unsigned* As = smem + (kt % NSTAGE) * STAGE_WORDS;
        const unsigned* Bs = As + TILE_WORDS;

#pragma unroll
        for (int k0 = 0; k0 < BK; k0 += 8) {
            unsigned a[2][4], b[8][2];
#pragma unroll
            for (int mi = 0; mi < 2; mi++) {
                int r = wm * 32 + mi * 16 + gid;
                a[mi][0] = As[r * LDS_W + k0 + tg];
                a[mi][1] = As[(r + 8) * LDS_W + k0 + tg];
                a[mi][2] = As[r * LDS_W + k0 + tg + 4];
                a[mi][3] = As[(r + 8) * LDS_W + k0 + tg + 4];
            }
#pragma unroll
            for (int ni = 0; ni < 8; ni++) {
                int n = wn * 64 + ni * 8 + gid;
                b[ni][0] = Bs[n * LDS_W + k0 + tg];
                b[ni][1] = Bs[n * LDS_W + k0 + tg + 4];
            }
#pragma unroll
            for (int mi = 0; mi < 2; mi++)
#pragma unroll
                for (int ni = 0; ni < 8; ni++)
                    MMA_TF32(acc[mi][ni], a[mi], b[ni]);
        }
    }

    // epilogue: bias + relu (+ tf32 round for next tensor layer)
#pragma unroll
    for (int mi = 0; mi < 2; mi++) {
#pragma unroll
        for (int ni = 0; ni < 8; ni++) {
            int r  = row0 + wm * 32 + mi * 16 + gid;
            int cl = col0 + wn * 64 + ni * 8 + 2 * tg;
            float b0 = __ldg(bias + cl), b1 = __ldg(bias + cl + 1);
            float v0 = fmaxf(acc[mi][ni][0] + b0, 0.f);
            float v1 = fmaxf(acc[mi][ni][1] + b1, 0.f);
            float v2 = fmaxf(acc[mi][ni][2] + b0, 0.f);
            float v3 = fmaxf(acc[mi][ni][3] + b1, 0.f);
            if (ROUND) {
                v0 = __uint_as_float(f2tf32(v0));
                v1 = __uint_as_float(f2tf32(v1));
                v2 = __uint_as_float(f2tf32(v2));
                v3 = __uint_as_float(f2tf32(v3));
            }
            *(float2*)(C + (size_t)r * N + cl)       = make_float2(v0, v1);
            *(float2*)(C + (size_t)(r + 8) * N + cl) = make_float2(v2, v3);
        }
    }
}

// ---------------------------------------------------------------------------
// Final head: out[b] = h[b,:] . Wo[0,:] + bo   (one warp per row, K=512)
// ---------------------------------------------------------------------------
__global__ void gemv_kernel(const float* __restrict__ h,
                            const float* __restrict__ w,
                            const float* __restrict__ b,
                            float* __restrict__ out) {
    int gw   = (blockIdx.x * blockDim.x + threadIdx.x) >> 5;
    int lane = threadIdx.x & 31;
    if (gw >= BATCH) return;
    const float4* hr = (const float4*)(h + (size_t)gw * 512);
    const float4* wr = (const float4*)w;
    float s = 0.f;
#pragma unroll
    for (int c = 0; c < 4; c++) {
        float4 hv = hr[c * 32 + lane];
        float4 wv = wr[c * 32 + lane];
        s += hv.x * wv.x + hv.y * wv.y + hv.z * wv.z + hv.w * wv.w;
    }
#pragma unroll
    for (int o = 16; o > 0; o >>= 1) s += __shfl_xor_sync(0xffffffffu, s, o);
    if (lane == 0) out[gw] = s + b[0];
}

// ---------------------------------------------------------------------------
extern "C" void kernel_launch(void* const* d_in, const int* in_sizes, int n_in,
                              void* d_out, int out_size) {
    (void)in_sizes; (void)n_in; (void)out_size;
    const float* x  = (const float*)d_in[0];
    const float* cw = (const float*)d_in[1];
    const float* cb = (const float*)d_in[2];
    const float* W1 = (const float*)d_in[3];  const float* b1 = (const float*)d_in[4];
    const float* W2 = (const float*)d_in[5];  const float* b2 = (const float*)d_in[6];
    const float* W3 = (const float*)d_in[7];  const float* b3 = (const float*)d_in[8];
    const float* W4 = (const float*)d_in[9];  const float* b4 = (const float*)d_in[10];
    const float* Wo = (const float*)d_in[11]; const float* bo = (const float*)d_in[12];

    float *buf0, *buf1, *w1, *w2, *w3, *w4;
    cudaGetSymbolAddress((void**)&buf0, g_buf0);
    cudaGetSymbolAddress((void**)&buf1, g_buf1);
    cudaGetSymbolAddress((void**)&w1, g_w1);
    cudaGetSymbolAddress((void**)&w2, g_w2);
    cudaGetSymbolAddress((void**)&w3, g_w3);
    cudaGetSymbolAddress((void**)&w4, g_w4);

    static int smem_set = 0;
    if (!smem_set) {
        cudaFuncSetAttribute(gemm_tf32<true>,
                             cudaFuncAttributeMaxDynamicSharedMemorySize, SMEM_BYTES);
        cudaFuncSetAttribute(gemm_tf32<false>,
                             cudaFuncAttributeMaxDynamicSharedMemorySize, SMEM_BYTES);
        smem_set = 1;
    }

    // pre-round weights to tf32 (once per launch; cheap)
    cvt_tf32_kernel<<<(2048 * 512 / 4 + 255) / 256, 256>>>(W1, w1, 2048 * 512 / 4);
    cvt_tf32_kernel<<<(2048 * 2048 / 4 + 255) / 256, 256>>>(W2, w2, 2048 * 2048 / 4);
    cvt_tf32_kernel<<<(1024 * 2048 / 4 + 255) / 256, 256>>>(W3, w3, 1024 * 2048 / 4);
    cvt_tf32_kernel<<<(512 * 1024 / 4 + 255) / 256, 256>>>(W4, w4, 512 * 1024 / 4);

    cross_kernel<<<BATCH / 8, 256>>>(x, cw, cb, buf0);

    gemm_tf32<true><<<dim3(2048 / BN, BATCH / BM), 256, SMEM_BYTES>>>(buf0, w1, b1, buf1,  512, 2048);
    gemm_tf32<true><<<dim3(2048 / BN, BATCH / BM), 256, SMEM_BYTES>>>(buf1, w2, b2, buf0, 2048, 2048);
    gemm_tf32<true><<<dim3(1024 / BN, BATCH / BM), 256, SMEM_BYTES>>>(buf0, w3, b3, buf1, 2048, 1024);
    gemm_tf32<false><<<dim3(512 / BN, BATCH / BM), 256, SMEM_BYTES>>>(buf1, w4, b4, buf0, 1024,  512);

    gemv_kernel<<<BATCH / 8, 256>>>(buf0, Wo, bo, (float*)d_out);
}

// round 4
// speedup vs baseline: 1.2263x; 1.0851x over previous
#include <cuda_runtime.h>
#include <cstdint>

#define BATCH 16384
#define IN_F  512

// Ping-pong scratch (max layer width 2048) + pre-rounded tf32 weights.
__device__ float g_buf0[BATCH * 2048];
__device__ float g_buf1[BATCH * 2048];
__device__ float g_w1[2048 * 512];
__device__ float g_w2[2048 * 2048];
__device__ float g_w3[1024 * 2048];
__device__ float g_w4[512 * 1024];

__device__ __forceinline__ unsigned f2tf32(float f) {
    unsigned r;
    asm("cvt.rna.tf32.f32 %0, %1;" : "=r"(r) : "f"(f));
    return r;
}
__device__ __forceinline__ uint32_t smem_u32(const void* p) {
    uint32_t a;
    asm("{ .reg .u64 t; cvta.to.shared.u64 t, %1; cvt.u32.u64 %0, t; }"
        : "=r"(a) : "l"(p));
    return a;
}

// ---------------------------------------------------------------------------
// Weight pre-round: out = tf32(in), vectorized
// ---------------------------------------------------------------------------
__global__ void cvt_tf32_kernel(const float* __restrict__ in,
                                float* __restrict__ out, int n4) {
    int i = blockIdx.x * blockDim.x + threadIdx.x;
    if (i >= n4) return;
    float4 v = ((const float4*)in)[i];
    float4 o;
    o.x = __uint_as_float(f2tf32(v.x));
    o.y = __uint_as_float(f2tf32(v.y));
    o.z = __uint_as_float(f2tf32(v.z));
    o.w = __uint_as_float(f2tf32(v.w));
    ((float4*)out)[i] = o;
}

// ---------------------------------------------------------------------------
// Cross layer: h = tf32( x * (x . cross_w) + cross_b + x )  (one warp per row)
// ---------------------------------------------------------------------------
__global__ void cross_kernel(const float* __restrict__ x,
                             const float* __restrict__ cw,
                             const float* __restrict__ cb,
                             float* __restrict__ out) {
    int gw   = (blockIdx.x * blockDim.x + threadIdx.x) >> 5;
    int lane = threadIdx.x & 31;
    if (gw >= BATCH) return;
    const float4* xr  = (const float4*)(x + (size_t)gw * IN_F);
    const float4* cwr = (const float4*)cw;
    float4 xv[4];
    float s = 0.f;
#pragma unroll
    for (int c = 0; c < 4; c++) {
        xv[c] = xr[c * 32 + lane];
        float4 w = cwr[c * 32 + lane];
        s += xv[c].x * w.x + xv[c].y * w.y + xv[c].z * w.z + xv[c].w * w.w;
    }
#pragma unroll
    for (int o = 16; o > 0; o >>= 1) s += __shfl_xor_sync(0xffffffffu, s, o);
    const float4* cbr = (const float4*)cb;
    float4* outr = (float4*)(out + (size_t)gw * IN_F);
#pragma unroll
    for (int c = 0; c < 4; c++) {
        float4 b = cbr[c * 32 + lane];
        float4 r;
        r.x = __uint_as_float(f2tf32(fmaf(xv[c].x, s, b.x) + xv[c].x));
        r.y = __uint_as_float(f2tf32(fmaf(xv[c].y, s, b.y) + xv[c].y));
        r.z = __uint_as_float(f2tf32(fmaf(xv[c].z, s, b.z) + xv[c].z));
        r.w = __uint_as_float(f2tf32(fmaf(xv[c].w, s, b.w) + xv[c].w));
        outr[c * 32 + lane] = r;
    }
}

// ---------------------------------------------------------------------------
// TF32 tensor-core GEMM, cp.async 3-stage pipeline + ldmatrix fragment loads.
//   C[M,N] = relu(A[M,K] @ W[N,K]^T + bias),  A/W pre-rounded to tf32.
// BM=BN=128, BK=32; 256 threads (8 warps 4x2), warp tile 32x64 (m16n8k8).
// Smem row stride 36 words -> conflict-free ldmatrix phases (banks 4r+c).
// ---------------------------------------------------------------------------
#define BM 128
#define BN 128
#define BK 32
#define LDS_W 36
#define NSTAGE 3
#define TILE_WORDS (BM * LDS_W)                 // 4608 words
#define STAGE_WORDS (2 * TILE_WORDS)            // 9216 words = 36864 B
#define SMEM_BYTES (NSTAGE * STAGE_WORDS * 4)   // 110592 B

#define MMA_TF32(c, a, b)                                                     \
    asm volatile(                                                             \
        "mma.sync.aligned.m16n8k8.row.col.f32.tf32.tf32.f32 "                 \
        "{%0,%1,%2,%3},{%4,%5,%6,%7},{%8,%9},{%0,%1,%2,%3};"                  \
        : "+f"(c[0]), "+f"(c[1]), "+f"(c[2]), "+f"(c[3])                      \
        : "r"(a[0]), "r"(a[1]), "r"(a[2]), "r"(a[3]), "r"(b[0]), "r"(b[1]))

#define LDSM4(r0, r1, r2, r3, addr)                                           \
    asm volatile("ldmatrix.sync.aligned.m8n8.x4.shared.b16 {%0,%1,%2,%3}, [%4];" \
                 : "=r"(r0), "=r"(r1), "=r"(r2), "=r"(r3) : "r"(addr))

#define CP16(dst, src)                                                        \
    asm volatile("cp.async.cg.shared.global [%0], [%1], 16;"                  \
                 :: "r"(dst), "l"(src))

template <bool ROUND>
__global__ __launch_bounds__(256, 2)
void gemm_tf32(const float* __restrict__ A, const float* __restrict__ W,
               const float* __restrict__ bias, float* __restrict__ C,
               int K, int N) {
    extern __shared__ unsigned smem[];
    const uint32_t sbase = smem_u32(smem);
    const int tid = threadIdx.x;
    const int warp = tid >> 5, lane = tid & 31;
    const int wm = warp >> 1, wn = warp & 1;
    const int gid = lane >> 2, tg = lane & 3;
    const int row0 = blockIdx.y * BM;
    const int col0 = blockIdx.x * BN;

    // cp.async producer coords
    const int lm  = tid >> 3;
    const int lk4 = (tid & 7) << 2;
    const float* Abase = A + (size_t)(row0 + lm) * K + lk4;
    const float* Wbase = W + (size_t)(col0 + lm) * K + lk4;
    const uint32_t soff = (lm * LDS_W + lk4) * 4;

    // ldmatrix per-lane byte offsets (within A/B tile)
    // A x4 #0: regs = a[0..3] of mi tile: lanes 0-7 rows 0-7 colL, 8-15 rows 8-15 colL,
    //          16-23 rows 0-7 colR, 24-31 rows 8-15 colR
    const uint32_t aoff0 =
        ((wm * 32 + (lane & 15)) * LDS_W + ((lane >> 4) << 2)) * 4;
    const uint32_t aoff1 = aoff0 + 16 * LDS_W * 4;
    // B x4 #j: regs = b[2j][0], b[2j][1], b[2j+1][0], b[2j+1][1]
    const uint32_t boffb =
        ((wn * 64 + (lane & 7) + ((lane & 16) ? 8 : 0)) * LDS_W +
         ((lane & 8) ? 4 : 0)) * 4;

    const int T = K / BK;

#define ISSUE_STAGE(kt)                                                       \
    do {                                                                      \
        uint32_t _sA = sbase + ((kt) % NSTAGE) * (STAGE_WORDS * 4);           \
        uint32_t _sB = _sA + TILE_WORDS * 4;                                  \
        const float* _Ag = Abase + (size_t)(kt) * BK;                         \
        const float* _Wg = Wbase + (size_t)(kt) * BK;                         \
        CP16(_sA + soff,                  _Ag);                               \
        CP16(_sA + soff + 32 * LDS_W * 4, _Ag + (size_t)32 * K);              \
        CP16(_sA + soff + 64 * LDS_W * 4, _Ag + (size_t)64 * K);              \
        CP16(_sA + soff + 96 * LDS_W * 4, _Ag + (size_t)96 * K);              \
        CP16(_sB + soff,                  _Wg);                               \
        CP16(_sB + soff + 32 * LDS_W * 4, _Wg + (size_t)32 * K);              \
        CP16(_sB + soff + 64 * LDS_W * 4, _Wg + (size_t)64 * K);              \
        CP16(_sB + soff + 96 * LDS_W * 4, _Wg + (size_t)96 * K);              \
        asm volatile("cp.async.commit_group;" ::: "memory");                  \
    } while (0)

    float acc[2][8][4];
#pragma unroll
    for (int mi = 0; mi < 2; mi++)
#pragma unroll
        for (int ni = 0; ni < 8; ni++)
#pragma unroll
            for (int e = 0; e < 4; e++) acc[mi][ni][e] = 0.f;

    ISSUE_STAGE(0);
    ISSUE_STAGE(1);

    for (int kt = 0; kt < T; kt++) {
        if (kt < T - 1)
            asm volatile("cp.async.wait_group 1;" ::: "memory");
        else
            asm volatile("cp.async.wait_group 0;" ::: "memory");
        __syncthreads();

        if (kt + 2 < T) ISSUE_STAGE(kt + 2);

        const uint32_t sA = sbase + (kt % NSTAGE) * (STAGE_WORDS * 4);
        const uint32_t sB = sA + TILE_WORDS * 4;

#pragma unroll
        for (int k0 = 0; k0 < BK; k0 += 8) {
            unsigned a[2][4], b[8][2];
            LDSM4(a[0][0], a[0][1], a[0][2], a[0][3], sA + aoff0 + k0 * 4);
            LDSM4(a[1][0], a[1][1], a[1][2], a[1][3], sA + aoff1 + k0 * 4);
#pragma unroll
            for (int j = 0; j < 4; j++)
                LDSM4(b[2 * j][0], b[2 * j][1], b[2 * j + 1][0], b[2 * j + 1][1],
                      sB + boffb + (16 * j * LDS_W + k0) * 4);
#pragma unroll
            for (int mi = 0; mi < 2; mi++)
#pragma unroll
                for (int ni = 0; ni < 8; ni++)
                    MMA_TF32(acc[mi][ni], a[mi], b[ni]);
        }
    }

    // epilogue: bias + relu (+ tf32 round for next tensor layer)
#pragma unroll
    for (int mi = 0; mi < 2; mi++) {
#pragma unroll
        for (int ni = 0; ni < 8; ni++) {
            int r  = row0 + wm * 32 + mi * 16 + gid;
            int cl = col0 + wn * 64 + ni * 8 + 2 * tg;
            float b0 = __ldg(bias + cl), b1 = __ldg(bias + cl + 1);
            float v0 = fmaxf(acc[mi][ni][0] + b0, 0.f);
            float v1 = fmaxf(acc[mi][ni][1] + b1, 0.f);
            float v2 = fmaxf(acc[mi][ni][2] + b0, 0.f);
            float v3 = fmaxf(acc[mi][ni][3] + b1, 0.f);
            if (ROUND) {
                v0 = __uint_as_float(f2tf32(v0));
                v1 = __uint_as_float(f2tf32(v1));
                v2 = __uint_as_float(f2tf32(v2));
                v3 = __uint_as_float(f2tf32(v3));
            }
            *(float2*)(C + (size_t)r * N + cl)       = make_float2(v0, v1);
            *(float2*)(C + (size_t)(r + 8) * N + cl) = make_float2(v2, v3);
        }
    }
}

// ---------------------------------------------------------------------------
// Final head: out[b] = h[b,:] . Wo[0,:] + bo   (one warp per row, K=512)
// ---------------------------------------------------------------------------
__global__ void gemv_kernel(const float* __restrict__ h,
                            const float* __restrict__ w,
                            const float* __restrict__ b,
                            float* __restrict__ out) {
    int gw   = (blockIdx.x * blockDim.x + threadIdx.x) >> 5;
    int lane = threadIdx.x & 31;
    if (gw >= BATCH) return;
    const float4* hr = (const float4*)(h + (size_t)gw * 512);
    const float4* wr = (const float4*)w;
    float s = 0.f;
#pragma unroll
    for (int c = 0; c < 4; c++) {
        float4 hv = hr[c * 32 + lane];
        float4 wv = wr[c * 32 + lane];
        s += hv.x * wv.x + hv.y * wv.y + hv.z * wv.z + hv.w * wv.w;
    }
#pragma unroll
    for (int o = 16; o > 0; o >>= 1) s += __shfl_xor_sync(0xffffffffu, s, o);
    if (lane == 0) out[gw] = s + b[0];
}

// ---------------------------------------------------------------------------
extern "C" void kernel_launch(void* const* d_in, const int* in_sizes, int n_in,
                              void* d_out, int out_size) {
    (void)in_sizes; (void)n_in; (void)out_size;
    const float* x  = (const float*)d_in[0];
    const float* cw = (const float*)d_in[1];
    const float* cb = (const float*)d_in[2];
    const float* W1 = (const float*)d_in[3];  const float* b1 = (const float*)d_in[4];
    const float* W2 = (const float*)d_in[5];  const float* b2 = (const float*)d_in[6];
    const float* W3 = (const float*)d_in[7];  const float* b3 = (const float*)d_in[8];
    const float* W4 = (const float*)d_in[9];  const float* b4 = (const float*)d_in[10];
    const float* Wo = (const float*)d_in[11]; const float* bo = (const float*)d_in[12];

    float *buf0, *buf1, *w1, *w2, *w3, *w4;
    cudaGetSymbolAddress((void**)&buf0, g_buf0);
    cudaGetSymbolAddress((void**)&buf1, g_buf1);
    cudaGetSymbolAddress((void**)&w1, g_w1);
    cudaGetSymbolAddress((void**)&w2, g_w2);
    cudaGetSymbolAddress((void**)&w3, g_w3);
    cudaGetSymbolAddress((void**)&w4, g_w4);

    static int smem_set = 0;
    if (!smem_set) {
        cudaFuncSetAttribute(gemm_tf32<true>,
                             cudaFuncAttributeMaxDynamicSharedMemorySize, SMEM_BYTES);
        cudaFuncSetAttribute(gemm_tf32<false>,
                             cudaFuncAttributeMaxDynamicSharedMemorySize, SMEM_BYTES);
        smem_set = 1;
    }

    // pre-round weights to tf32 (once per launch; cheap)
    cvt_tf32_kernel<<<(2048 * 512 / 4 + 255) / 256, 256>>>(W1, w1, 2048 * 512 / 4);
    cvt_tf32_kernel<<<(2048 * 2048 / 4 + 255) / 256, 256>>>(W2, w2, 2048 * 2048 / 4);
    cvt_tf32_kernel<<<(1024 * 2048 / 4 + 255) / 256, 256>>>(W3, w3, 1024 * 2048 / 4);
    cvt_tf32_kernel<<<(512 * 1024 / 4 + 255) / 256, 256>>>(W4, w4, 512 * 1024 / 4);

    cross_kernel<<<BATCH / 8, 256>>>(x, cw, cb, buf0);

    gemm_tf32<true><<<dim3(2048 / BN, BATCH / BM), 256, SMEM_BYTES>>>(buf0, w1, b1, buf1,  512, 2048);
    gemm_tf32<true><<<dim3(2048 / BN, BATCH / BM), 256, SMEM_BYTES>>>(buf1, w2, b2, buf0, 2048, 2048);
    gemm_tf32<true><<<dim3(1024 / BN, BATCH / BM), 256, SMEM_BYTES>>>(buf0, w3, b3, buf1, 2048, 1024);
    gemm_tf32<false><<<dim3(512 / BN, BATCH / BM), 256, SMEM_BYTES>>>(buf1, w4, b4, buf0, 1024,  512);

    gemv_kernel<<<BATCH / 8, 256>>>(buf0, Wo, bo, (float*)d_out);
}

// round 6
// speedup vs baseline: 2.3933x; 1.9517x over previous
#include <cuda_runtime.h>
#include <cuda_fp16.h>
#include <cstdint>

#define BATCH 16384
#define IN_F  512

// Ping-pong scratch (raw, reinterpreted as half or float) + fp16 weights.
__device__ float g_buf0[BATCH * 2048];
__device__ float g_buf1[BATCH * 2048];
__device__ float g_w1[2048 * 512];
__device__ float g_w2[2048 * 2048];
__device__ float g_w3[1024 * 2048];
__device__ float g_w4[512 * 1024];

__device__ __forceinline__ uint32_t smem_u32(const void* p) {
    uint32_t a;
    asm("{ .reg .u64 t; cvta.to.shared.u64 t, %1; cvt.u32.u64 %0, t; }"
        : "=r"(a) : "l"(p));
    return a;
}

// ---------------------------------------------------------------------------
// Weight convert: float -> half
// ---------------------------------------------------------------------------
__global__ void cvt_f16_kernel(const float* __restrict__ in,
                               __half* __restrict__ out, int n4) {
    int i = blockIdx.x * blockDim.x + threadIdx.x;
    if (i >= n4) return;
    float4 v = ((const float4*)in)[i];
    __half2 h0 = __floats2half2_rn(v.x, v.y);
    __half2 h1 = __floats2half2_rn(v.z, v.w);
    ((uint2*)out)[i] = make_uint2(*(uint32_t*)&h0, *(uint32_t*)&h1);
}

// ---------------------------------------------------------------------------
// Cross layer: h = half( x * (x . cross_w) + cross_b + x )  (one warp per row)
// ---------------------------------------------------------------------------
__global__ void cross_kernel(const float* __restrict__ x,
                             const float* __restrict__ cw,
                             const float* __restrict__ cb,
                             __half* __restrict__ out) {
    int gw   = (blockIdx.x * blockDim.x + threadIdx.x) >> 5;
    int lane = threadIdx.x & 31;
    if (gw >= BATCH) return;
    const float4* xr  = (const float4*)(x + (size_t)gw * IN_F);
    const float4* cwr = (const float4*)cw;
    float4 xv[4];
    float s = 0.f;
#pragma unroll
    for (int c = 0; c < 4; c++) {
        xv[c] = xr[c * 32 + lane];
        float4 w = cwr[c * 32 + lane];
        s += xv[c].x * w.x + xv[c].y * w.y + xv[c].z * w.z + xv[c].w * w.w;
    }
#pragma unroll
    for (int o = 16; o > 0; o >>= 1) s += __shfl_xor_sync(0xffffffffu, s, o);
    const float4* cbr = (const float4*)cb;
    uint2* outr = (uint2*)(out + (size_t)gw * IN_F);
#pragma unroll
    for (int c = 0; c < 4; c++) {
        float4 b = cbr[c * 32 + lane];
        __half2 h0 = __floats2half2_rn(fmaf(xv[c].x, s, b.x) + xv[c].x,
                                       fmaf(xv[c].y, s, b.y) + xv[c].y);
        __half2 h1 = __floats2half2_rn(fmaf(xv[c].z, s, b.z) + xv[c].z,
                                       fmaf(xv[c].w, s, b.w) + xv[c].w);
        outr[c * 32 + lane] = make_uint2(*(uint32_t*)&h0, *(uint32_t*)&h1);
    }
}

// ---------------------------------------------------------------------------
// FP16 tensor-core GEMM (fp32 accum), cp.async 3-stage + ldmatrix + swizzle.
//   C[M,N] = relu(A[M,K] @ W[N,K]^T + bias);  A, W are __half.
// BM=BN=128, BK=32 (64B rows); 256 threads (8 warps 4x2), warp tile 32x64,
// m16n8k16. Swizzle: 16B chunk c of row r -> c ^ ((r>>1)&3). Conflict-free
// for ldmatrix phases AND cp.async store phases.
// ---------------------------------------------------------------------------
#define BM 128
#define BN 128
#define BK 32
#define NSTAGE 3
#define TILE_BYTES (BM * 64)                     // 8192 B per operand tile
#define STAGE_BYTES (2 * TILE_BYTES)             // 16384 B
#define SMEM_BYTES (NSTAGE * STAGE_BYTES)        // 49152 B

#define MMA_F16(c, a, b)                                                      \
    asm volatile(                                                             \
        "mma.sync.aligned.m16n8k16.row.col.f32.f16.f16.f32 "                  \
        "{%0,%1,%2,%3},{%4,%5,%6,%7},{%8,%9},{%0,%1,%2,%3};"                  \
        : "+f"(c[0]), "+f"(c[1]), "+f"(c[2]), "+f"(c[3])                      \
        : "r"(a[0]), "r"(a[1]), "r"(a[2]), "r"(a[3]), "r"(b[0]), "r"(b[1]))

#define LDSM4(r0, r1, r2, r3, addr)                                           \
    asm volatile("ldmatrix.sync.aligned.m8n8.x4.shared.b16 {%0,%1,%2,%3}, [%4];" \
                 : "=r"(r0), "=r"(r1), "=r"(r2), "=r"(r3) : "r"(addr))

#define CP16(dst, src)                                                        \
    asm volatile("cp.async.cg.shared.global [%0], [%1], 16;"                  \
                 :: "r"(dst), "l"(src))

// swizzled byte offset of 16B chunk c in row r (64B rows)
__device__ __forceinline__ uint32_t swz(int r, int c) {
    return (uint32_t)(r * 64 + ((c ^ ((r >> 1) & 3)) * 16));
}

template <bool HALF_OUT>
__global__ __launch_bounds__(256, 2)
void gemm_f16(const __half* __restrict__ A, const __half* __restrict__ W,
              const float* __restrict__ bias, void* __restrict__ Cout,
              int K, int N) {
    extern __shared__ char smem[];
    const uint32_t sbase = smem_u32(smem);
    const int tid = threadIdx.x;
    const int warp = tid >> 5, lane = tid & 31;
    const int wm = warp >> 1, wn = warp & 1;
    const int gid = lane >> 2, tg = lane & 3;
    const int row0 = blockIdx.y * BM;
    const int col0 = blockIdx.x * BN;

    // cp.async producer coords: i = tid (+256): row = i>>2 (0..127), chunk = i&3
    const int pr = tid >> 2;            // 0..63
    const int pc = tid & 3;
    const __half* Abase = A + (size_t)(row0 + pr) * K + pc * 8;
    const __half* Wbase = W + (size_t)(col0 + pr) * K + pc * 8;
    const uint32_t pd = swz(pr, pc);    // same xor mask for pr and pr+64

    // ldmatrix lane coords
    const int arowA = wm * 32 + (lane & 15);         // + kstep chunk (lane>>4)
    const int acA   = lane >> 4;
    const int arowB = wn * 64 + (lane & 7) + ((lane & 16) ? 8 : 0);
    const int acB   = (lane & 8) ? 1 : 0;

    const int T = K / BK;

#define ISSUE_STAGE(kt)                                                       \
    do {                                                                      \
        uint32_t _sA = sbase + ((kt) % NSTAGE) * STAGE_BYTES;                 \
        uint32_t _sB = _sA + TILE_BYTES;                                      \
        const __half* _Ag = Abase + (size_t)(kt) * BK;                        \
        const __half* _Wg = Wbase + (size_t)(kt) * BK;                        \
        CP16(_sA + pd,        _Ag);                                           \
        CP16(_sA + pd + 4096, _Ag + (size_t)64 * K);                          \
        CP16(_sB + pd,        _Wg);                                           \
        CP16(_sB + pd + 4096, _Wg + (size_t)64 * K);                          \
        asm volatile("cp.async.commit_group;" ::: "memory");                  \
    } while (0)

    float acc[2][8][4];
#pragma unroll
    for (int mi = 0; mi < 2; mi++)
#pragma unroll
        for (int ni = 0; ni < 8; ni++)
#pragma unroll
            for (int e = 0; e < 4; e++) acc[mi][ni][e] = 0.f;

    ISSUE_STAGE(0);
    ISSUE_STAGE(1);

    for (int kt = 0; kt < T; kt++) {
        if (kt < T - 1)
            asm volatile("cp.async.wait_group 1;" ::: "memory");
        else
            asm volatile("cp.async.wait_group 0;" ::: "memory");
        __syncthreads();

        if (kt + 2 < T) ISSUE_STAGE(kt + 2);

        const uint32_t sA = sbase + (kt % NSTAGE) * STAGE_BYTES;
        const uint32_t sB = sA + TILE_BYTES;

#pragma unroll
        for (int ks = 0; ks < 2; ks++) {            // two k16 steps per tile
            unsigned a[2][4], b[8][2];
            LDSM4(a[0][0], a[0][1], a[0][2], a[0][3],
                  sA + swz(arowA,      ks * 2 + acA));
            LDSM4(a[1][0], a[1][1], a[1][2], a[1][3],
                  sA + swz(arowA + 16, ks * 2 + acA));
#pragma unroll
            for (int j = 0; j < 4; j++)
                LDSM4(b[2 * j][0], b[2 * j][1], b[2 * j + 1][0], b[2 * j + 1][1],
                      sB + swz(arowB + 16 * j, ks * 2 + acB));
#pragma unroll
            for (int mi = 0; mi < 2; mi++)
#pragma unroll
                for (int ni = 0; ni < 8; ni++)
                    MMA_F16(acc[mi][ni], a[mi], b[ni]);
        }
    }

    // epilogue: bias + relu; half2 stores (hidden layers) or float2 (last)
#pragma unroll
    for (int mi = 0; mi < 2; mi++) {
#pragma unroll
        for (int ni = 0; ni < 8; ni++) {
            int r  = row0 + wm * 32 + mi * 16 + gid;
            int cl = col0 + wn * 64 + ni * 8 + 2 * tg;
            float b0 = __ldg(bias + cl), b1 = __ldg(bias + cl + 1);
            float v0 = fmaxf(acc[mi][ni][0] + b0, 0.f);
            float v1 = fmaxf(acc[mi][ni][1] + b1, 0.f);
            float v2 = fmaxf(acc[mi][ni][2] + b0, 0.f);
            float v3 = fmaxf(acc[mi][ni][3] + b1, 0.f);
            if (HALF_OUT) {
                __half* Ch = (__half*)Cout;
                __half2 h01 = __floats2half2_rn(v0, v1);
                __half2 h23 = __floats2half2_rn(v2, v3);
                *(__half2*)(Ch + (size_t)r * N + cl)       = h01;
                *(__half2*)(Ch + (size_t)(r + 8) * N + cl) = h23;
            } else {
                float* Cf = (float*)Cout;
                *(float2*)(Cf + (size_t)r * N + cl)       = make_float2(v0, v1);
                *(float2*)(Cf + (size_t)(r + 8) * N + cl) = make_float2(v2, v3);
            }
        }
    }
}

// ---------------------------------------------------------------------------
// Final head: out[b] = h[b,:] . Wo[0,:] + bo   (one warp per row, K=512, fp32)
// ---------------------------------------------------------------------------
__global__ void gemv_kernel(const float* __restrict__ h,
                            const float* __restrict__ w,
                            const float* __restrict__ b,
                            float* __restrict__ out) {
    int gw   = (blockIdx.x * blockDim.x + threadIdx.x) >> 5;
    int lane = threadIdx.x & 31;
    if (gw >= BATCH) return;
    const float4* hr = (const float4*)(h + (size_t)gw * 512);
    const float4* wr = (const float4*)w;
    float s = 0.f;
#pragma unroll
    for (int c = 0; c < 4; c++) {
        float4 hv = hr[c * 32 + lane];
        float4 wv = wr[c * 32 + lane];
        s += hv.x * wv.x + hv.y * wv.y + hv.z * wv.z + hv.w * wv.w;
    }
#pragma unroll
    for (int o = 16; o > 0; o >>= 1) s += __shfl_xor_sync(0xffffffffu, s, o);
    if (lane == 0) out[gw] = s + b[0];
}

// ---------------------------------------------------------------------------
extern "C" void kernel_launch(void* const* d_in, const int* in_sizes, int n_in,
                              void* d_out, int out_size) {
    (void)in_sizes; (void)n_in; (void)out_size;
    const float* x  = (const float*)d_in[0];
    const float* cw = (const float*)d_in[1];
    const float* cb = (const float*)d_in[2];
    const float* W1 = (const float*)d_in[3];  const float* b1 = (const float*)d_in[4];
    const float* W2 = (const float*)d_in[5];  const float* b2 = (const float*)d_in[6];
    const float* W3 = (const float*)d_in[7];  const float* b3 = (const float*)d_in[8];
    const float* W4 = (const float*)d_in[9];  const float* b4 = (const float*)d_in[10];
    const float* Wo = (const float*)d_in[11]; const float* bo = (const float*)d_in[12];

    float *buf0, *buf1, *w1f, *w2f, *w3f, *w4f;
    cudaGetSymbolAddress((void**)&buf0, g_buf0);
    cudaGetSymbolAddress((void**)&buf1, g_buf1);
    cudaGetSymbolAddress((void**)&w1f, g_w1);
    cudaGetSymbolAddress((void**)&w2f, g_w2);
    cudaGetSymbolAddress((void**)&w3f, g_w3);
    cudaGetSymbolAddress((void**)&w4f, g_w4);
    __half* h0 = (__half*)buf0;
    __half* h1 = (__half*)buf1;
    __half* w1 = (__half*)w1f;  __half* w2 = (__half*)w2f;
    __half* w3 = (__half*)w3f;  __half* w4 = (__half*)w4f;

    static int smem_set = 0;
    if (!smem_set) {
        cudaFuncSetAttribute(gemm_f16<true>,
                             cudaFuncAttributeMaxDynamicSharedMemorySize, SMEM_BYTES);
        cudaFuncSetAttribute(gemm_f16<false>,
                             cudaFuncAttributeMaxDynamicSharedMemorySize, SMEM_BYTES);
        smem_set = 1;
    }

    // weights -> fp16 (once per launch; ~4 GB/s-scale, negligible)
    cvt_f16_kernel<<<(2048 * 512 / 4 + 255) / 256, 256>>>(W1, w1, 2048 * 512 / 4);
    cvt_f16_kernel<<<(2048 * 2048 / 4 + 255) / 256, 256>>>(W2, w2, 2048 * 2048 / 4);
    cvt_f16_kernel<<<(1024 * 2048 / 4 + 255) / 256, 256>>>(W3, w3, 1024 * 2048 / 4);
    cvt_f16_kernel<<<(512 * 1024 / 4 + 255) / 256, 256>>>(W4, w4, 512 * 1024 / 4);

    cross_kernel<<<BATCH / 8, 256>>>(x, cw, cb, h0);

    gemm_f16<true ><<<dim3(2048 / BN, BATCH / BM), 256, SMEM_BYTES>>>(h0, w1, b1, h1,   512, 2048);
    gemm_f16<true ><<<dim3(2048 / BN, BATCH / BM), 256, SMEM_BYTES>>>(h1, w2, b2, h0,  2048, 2048);
    gemm_f16<true ><<<dim3(1024 / BN, BATCH / BM), 256, SMEM_BYTES>>>(h0, w3, b3, h1,  2048, 1024);
    gemm_f16<false><<<dim3( 512 / BN, BATCH / BM), 256, SMEM_BYTES>>>(h1, w4, b4, buf0, 1024,  512);

    gemv_kernel<<<BATCH / 8, 256>>>(buf0, Wo, bo, (float*)d_out);
}

// round 7
// speedup vs baseline: 2.7517x; 1.1498x over previous
#include <cuda_runtime.h>
#include <cuda_fp16.h>
#include <cstdint>

#define BATCH 16384
#define IN_F  512

// Ping-pong scratch (raw, reinterpreted as half or float) + fp16 weights.
__device__ float g_buf0[BATCH * 2048];
__device__ float g_buf1[BATCH * 2048];
__device__ float g_w1[2048 * 512];
__device__ float g_w2[2048 * 2048];
__device__ float g_w3[1024 * 2048];
__device__ float g_w4[512 * 1024];

__device__ __forceinline__ uint32_t smem_u32(const void* p) {
    uint32_t a;
    asm("{ .reg .u64 t; cvta.to.shared.u64 t, %1; cvt.u32.u64 %0, t; }"
        : "=r"(a) : "l"(p));
    return a;
}

// ---------------------------------------------------------------------------
// Weight convert: float -> half
// ---------------------------------------------------------------------------
__global__ void cvt_f16_kernel(const float* __restrict__ in,
                               __half* __restrict__ out, int n4) {
    int i = blockIdx.x * blockDim.x + threadIdx.x;
    if (i >= n4) return;
    float4 v = ((const float4*)in)[i];
    __half2 h0 = __floats2half2_rn(v.x, v.y);
    __half2 h1 = __floats2half2_rn(v.z, v.w);
    ((uint2*)out)[i] = make_uint2(*(uint32_t*)&h0, *(uint32_t*)&h1);
}

// ---------------------------------------------------------------------------
// Cross layer: h = half( x * (x . cross_w) + cross_b + x )  (one warp per row)
// ---------------------------------------------------------------------------
__global__ void cross_kernel(const float* __restrict__ x,
                             const float* __restrict__ cw,
                             const float* __restrict__ cb,
                             __half* __restrict__ out) {
    int gw   = (blockIdx.x * blockDim.x + threadIdx.x) >> 5;
    int lane = threadIdx.x & 31;
    if (gw >= BATCH) return;
    const float4* xr  = (const float4*)(x + (size_t)gw * IN_F);
    const float4* cwr = (const float4*)cw;
    float4 xv[4];
    float s = 0.f;
#pragma unroll
    for (int c = 0; c < 4; c++) {
        xv[c] = xr[c * 32 + lane];
        float4 w = cwr[c * 32 + lane];
        s += xv[c].x * w.x + xv[c].y * w.y + xv[c].z * w.z + xv[c].w * w.w;
    }
#pragma unroll
    for (int o = 16; o > 0; o >>= 1) s += __shfl_xor_sync(0xffffffffu, s, o);
    const float4* cbr = (const float4*)cb;
    uint2* outr = (uint2*)(out + (size_t)gw * IN_F);
#pragma unroll
    for (int c = 0; c < 4; c++) {
        float4 b = cbr[c * 32 + lane];
        __half2 h0 = __floats2half2_rn(fmaf(xv[c].x, s, b.x) + xv[c].x,
                                       fmaf(xv[c].y, s, b.y) + xv[c].y);
        __half2 h1 = __floats2half2_rn(fmaf(xv[c].z, s, b.z) + xv[c].z,
                                       fmaf(xv[c].w, s, b.w) + xv[c].w);
        outr[c * 32 + lane] = make_uint2(*(uint32_t*)&h0, *(uint32_t*)&h1);
    }
}

// ---------------------------------------------------------------------------
// FP16 tensor-core GEMM (fp32 accum), cp.async 4-stage + ldmatrix + swizzle.
//   C[M,N] = relu(A[M,K] @ W[N,K]^T + bias);  A, W are __half.
// BM=BN=128, BK=32 (64B rows); 128 threads (4 warps 2x2), warp tile 64x64,
// m16n8k16. Swizzle: 16B chunk c of row r -> c ^ ((r>>1)&3). Conflict-free
// for ldmatrix phases AND cp.async store phases. 2 CTAs/SM.
// ---------------------------------------------------------------------------
#define BM 128
#define BN 128
#define BK 32
#define NSTAGE 4
#define TILE_BYTES (BM * 64)                     // 8192 B per operand tile
#define STAGE_BYTES (2 * TILE_BYTES)             // 16384 B
#define SMEM_BYTES (NSTAGE * STAGE_BYTES)        // 65536 B

#define MMA_F16(c, a, b)                                                      \
    asm volatile(                                                             \
        "mma.sync.aligned.m16n8k16.row.col.f32.f16.f16.f32 "                  \
        "{%0,%1,%2,%3},{%4,%5,%6,%7},{%8,%9},{%0,%1,%2,%3};"                  \
        : "+f"(c[0]), "+f"(c[1]), "+f"(c[2]), "+f"(c[3])                      \
        : "r"(a[0]), "r"(a[1]), "r"(a[2]), "r"(a[3]), "r"(b[0]), "r"(b[1]))

#define LDSM4(r0, r1, r2, r3, addr)                                           \
    asm volatile("ldmatrix.sync.aligned.m8n8.x4.shared.b16 {%0,%1,%2,%3}, [%4];" \
                 : "=r"(r0), "=r"(r1), "=r"(r2), "=r"(r3) : "r"(addr))

#define CP16(dst, src)                                                        \
    asm volatile("cp.async.cg.shared.global [%0], [%1], 16;"                  \
                 :: "r"(dst), "l"(src))

// swizzled byte offset of 16B chunk c in row r (64B rows)
__device__ __forceinline__ uint32_t swz(int r, int c) {
    return (uint32_t)(r * 64 + ((c ^ ((r >> 1) & 3)) * 16));
}

template <bool HALF_OUT>
__global__ __launch_bounds__(128, 2)
void gemm_f16(const __half* __restrict__ A, const __half* __restrict__ W,
              const float* __restrict__ bias, void* __restrict__ Cout,
              int K, int N) {
    extern __shared__ char smem[];
    const uint32_t sbase = smem_u32(smem);
    const int tid = threadIdx.x;
    const int warp = tid >> 5, lane = tid & 31;
    const int wm = warp >> 1, wn = warp & 1;     // 2x2 grid of 64x64 tiles
    const int gid = lane >> 2, tg = lane & 3;
    const int row0 = blockIdx.y * BM;
    const int col0 = blockIdx.x * BN;

    // cp.async producer coords: pr = tid>>2 (0..31), 4 rows each (+32 apart);
    // swizzle mask (r>>1)&3 is invariant under r+=32.
    const int pr = tid >> 2;
    const int pc = tid & 3;
    const __half* Abase = A + (size_t)(row0 + pr) * K + pc * 8;
    const __half* Wbase = W + (size_t)(col0 + pr) * K + pc * 8;
    const uint32_t pd = swz(pr, pc);

    // ldmatrix lane coords (same verified mapping as before)
    const int arowA = wm * 64 + (lane & 15);     // + mi*16
    const int acA   = lane >> 4;
    const int arowB = wn * 64 + (lane & 7) + ((lane & 16) ? 8 : 0);  // + 16j
    const int acB   = (lane & 8) ? 1 : 0;

    const int T = K / BK;

#define ISSUE_STAGE(kt)                                                       \
    do {                                                                      \
        uint32_t _sA = sbase + ((kt) % NSTAGE) * STAGE_BYTES;                 \
        uint32_t _sB = _sA + TILE_BYTES;                                      \
        const __half* _Ag = Abase + (size_t)(kt) * BK;                        \
        const __half* _Wg = Wbase + (size_t)(kt) * BK;                        \
        CP16(_sA + pd,        _Ag);                                           \
        CP16(_sA + pd + 2048, _Ag + (size_t)32 * K);                          \
        CP16(_sA + pd + 4096, _Ag + (size_t)64 * K);                          \
        CP16(_sA + pd + 6144, _Ag + (size_t)96 * K);                          \
        CP16(_sB + pd,        _Wg);                                           \
        CP16(_sB + pd + 2048, _Wg + (size_t)32 * K);                          \
        CP16(_sB + pd + 4096, _Wg + (size_t)64 * K);                          \
        CP16(_sB + pd + 6144, _Wg + (size_t)96 * K);                          \
        asm volatile("cp.async.commit_group;" ::: "memory");                  \
    } while (0)

    float acc[4][8][4];
#pragma unroll
    for (int mi = 0; mi < 4; mi++)
#pragma unroll
        for (int ni = 0; ni < 8; ni++)
#pragma unroll
            for (int e = 0; e < 4; e++) acc[mi][ni][e] = 0.f;

    ISSUE_STAGE(0);
    ISSUE_STAGE(1);
    ISSUE_STAGE(2);

    for (int kt = 0; kt < T; kt++) {
        if (kt + 2 < T)
            asm volatile("cp.async.wait_group 2;" ::: "memory");
        else if (kt + 1 < T)
            asm volatile("cp.async.wait_group 1;" ::: "memory");
        else
            asm volatile("cp.async.wait_group 0;" ::: "memory");
        __syncthreads();

        if (kt + 3 < T) ISSUE_STAGE(kt + 3);

        const uint32_t sA = sbase + (kt % NSTAGE) * STAGE_BYTES;
        const uint32_t sB = sA + TILE_BYTES;

#pragma unroll
        for (int ks = 0; ks < 2; ks++) {            // two k16 steps per tile
            unsigned a[4][4], b[8][2];
#pragma unroll
            for (int mi = 0; mi < 4; mi++)
                LDSM4(a[mi][0], a[mi][1], a[mi][2], a[mi][3],
                      sA + swz(arowA + 16 * mi, ks * 2 + acA));
#pragma unroll
            for (int j = 0; j < 4; j++)
                LDSM4(b[2 * j][0], b[2 * j][1], b[2 * j + 1][0], b[2 * j + 1][1],
                      sB + swz(arowB + 16 * j, ks * 2 + acB));
#pragma unroll
            for (int mi = 0; mi < 4; mi++)
#pragma unroll
                for (int ni = 0; ni < 8; ni++)
                    MMA_F16(acc[mi][ni], a[mi], b[ni]);
        }
    }

    // epilogue: bias + relu; half2 stores (hidden layers) or float2 (last)
#pragma unroll
    for (int mi = 0; mi < 4; mi++) {
#pragma unroll
        for (int ni = 0; ni < 8; ni++) {
            int r  = row0 + wm * 64 + mi * 16 + gid;
            int cl = col0 + wn * 64 + ni * 8 + 2 * tg;
            float b0 = __ldg(bias + cl), b1 = __ldg(bias + cl + 1);
            float v0 = fmaxf(acc[mi][ni][0] + b0, 0.f);
            float v1 = fmaxf(acc[mi][ni][1] + b1, 0.f);
            float v2 = fmaxf(acc[mi][ni][2] + b0, 0.f);
            float v3 = fmaxf(acc[mi][ni][3] + b1, 0.f);
            if (HALF_OUT) {
                __half* Ch = (__half*)Cout;
                __half2 h01 = __floats2half2_rn(v0, v1);
                __half2 h23 = __floats2half2_rn(v2, v3);
                *(__half2*)(Ch + (size_t)r * N + cl)       = h01;
                *(__half2*)(Ch + (size_t)(r + 8) * N + cl) = h23;
            } else {
                float* Cf = (float*)Cout;
                *(float2*)(Cf + (size_t)r * N + cl)       = make_float2(v0, v1);
                *(float2*)(Cf + (size_t)(r + 8) * N + cl) = make_float2(v2, v3);
            }
        }
    }
}

// ---------------------------------------------------------------------------
// Final head: out[b] = h[b,:] . Wo[0,:] + bo   (one warp per row, K=512, fp32)
// ---------------------------------------------------------------------------
__global__ void gemv_kernel(const float* __restrict__ h,
                            const float* __restrict__ w,
                            const float* __restrict__ b,
                            float* __restrict__ out) {
    int gw   = (blockIdx.x * blockDim.x + threadIdx.x) >> 5;
    int lane = threadIdx.x & 31;
    if (gw >= BATCH) return;
    const float4* hr = (const float4*)(h + (size_t)gw * 512);
    const float4* wr = (const float4*)w;
    float s = 0.f;
#pragma unroll
    for (int c = 0; c < 4; c++) {
        float4 hv = hr[c * 32 + lane];
        float4 wv = wr[c * 32 + lane];
        s += hv.x * wv.x + hv.y * wv.y + hv.z * wv.z + hv.w * wv.w;
    }
#pragma unroll
    for (int o = 16; o > 0; o >>= 1) s += __shfl_xor_sync(0xffffffffu, s, o);
    if (lane == 0) out[gw] = s + b[0];
}

// ---------------------------------------------------------------------------
extern "C" void kernel_launch(void* const* d_in, const int* in_sizes, int n_in,
                              void* d_out, int out_size) {
    (void)in_sizes; (void)n_in; (void)out_size;
    const float* x  = (const float*)d_in[0];
    const float* cw = (const float*)d_in[1];
    const float* cb = (const float*)d_in[2];
    const float* W1 = (const float*)d_in[3];  const float* b1 = (const float*)d_in[4];
    const float* W2 = (const float*)d_in[5];  const float* b2 = (const float*)d_in[6];
    const float* W3 = (const float*)d_in[7];  const float* b3 = (const float*)d_in[8];
    const float* W4 = (const float*)d_in[9];  const float* b4 = (const float*)d_in[10];
    const float* Wo = (const float*)d_in[11]; const float* bo = (const float*)d_in[12];

    float *buf0, *buf1, *w1f, *w2f, *w3f, *w4f;
    cudaGetSymbolAddress((void**)&buf0, g_buf0);
    cudaGetSymbolAddress((void**)&buf1, g_buf1);
    cudaGetSymbolAddress((void**)&w1f, g_w1);
    cudaGetSymbolAddress((void**)&w2f, g_w2);
    cudaGetSymbolAddress((void**)&w3f, g_w3);
    cudaGetSymbolAddress((void**)&w4f, g_w4);
    __half* h0 = (__half*)buf0;
    __half* h1 = (__half*)buf1;
    __half* w1 = (__half*)w1f;  __half* w2 = (__half*)w2f;
    __half* w3 = (__half*)w3f;  __half* w4 = (__half*)w4f;

    static int smem_set = 0;
    if (!smem_set) {
        cudaFuncSetAttribute(gemm_f16<true>,
                             cudaFuncAttributeMaxDynamicSharedMemorySize, SMEM_BYTES);
        cudaFuncSetAttribute(gemm_f16<false>,
                             cudaFuncAttributeMaxDynamicSharedMemorySize, SMEM_BYTES);
        smem_set = 1;
    }

    // weights -> fp16 (once per launch; negligible)
    cvt_f16_kernel<<<(2048 * 512 / 4 + 255) / 256, 256>>>(W1, w1, 2048 * 512 / 4);
    cvt_f16_kernel<<<(2048 * 2048 / 4 + 255) / 256, 256>>>(W2, w2, 2048 * 2048 / 4);
    cvt_f16_kernel<<<(1024 * 2048 / 4 + 255) / 256, 256>>>(W3, w3, 1024 * 2048 / 4);
    cvt_f16_kernel<<<(512 * 1024 / 4 + 255) / 256, 256>>>(W4, w4, 512 * 1024 / 4);

    cross_kernel<<<BATCH / 8, 256>>>(x, cw, cb, h0);

    gemm_f16<true ><<<dim3(2048 / BN, BATCH / BM), 128, SMEM_BYTES>>>(h0, w1, b1, h1,   512, 2048);
    gemm_f16<true ><<<dim3(2048 / BN, BATCH / BM), 128, SMEM_BYTES>>>(h1, w2, b2, h0,  2048, 2048);
    gemm_f16<true ><<<dim3(1024 / BN, BATCH / BM), 128, SMEM_BYTES>>>(h0, w3, b3, h1,  2048, 1024);
    gemm_f16<false><<<dim3( 512 / BN, BATCH / BM), 128, SMEM_BYTES>>>(h1, w4, b4, buf0, 1024,  512);

    gemv_kernel<<<BATCH / 8, 256>>>(buf0, Wo, bo, (float*)d_out);
}